// round 16
// baseline (speedup 1.0000x reference)
#include <cuda_runtime.h>
#include <cuda_fp16.h>
#include <cstdint>

#define NN 100000
#define EE 800000

// ---------------- scratch (__device__ globals; no allocation allowed) ----------
__device__ float g_deg[NN];                       // dinv_sqrt
__device__ int   g_cnt[NN];                       // in-degree counts
__device__ int   g_off[NN + 1];                   // CSR offsets (by dst)
__device__ int   g_fill[NN];                      // fill cursors
__device__ int   g_csr[EE];                       // src ids grouped by dst
__device__ float g_nrm[EE];                       // per-edge norm deg[s]*deg[d]
__device__ int   g_bsum[512];                     // scan block sums
__device__ __align__(16) __half gX16[NN * 128];   // x in fp16 (agg1 gather source)
__device__ __align__(16) __half gA16[NN * 128];   // aggregated X, fp16 (GEMM1 A)
__device__ __align__(16) __half gH2[NN * 40];     // H @ W2, fp16 (agg2 source)
__device__ unsigned g_mask[800000];               // keep-bits for cols 0-255 only
__device__ __align__(16) __half gW1h[128 * 512];  // W1 fp16, k-major
__device__ __align__(16) __half gW2h[512 * 40];   // W2 fp16, k-major

// ---------------- small helpers ------------------------------------------------
__device__ __forceinline__ unsigned smem_u32(const void* p) {
    unsigned a;
    asm("{ .reg .u64 t; cvta.to.shared.u64 t, %1; cvt.u32.u64 %0, t; }" : "=r"(a) : "l"(p));
    return a;
}

// JAX threefry2x32 with key = (0, 42)
__device__ __forceinline__ void threefry42(unsigned& x0, unsigned& x1) {
    const unsigned ks0 = 0u, ks1 = 42u, ks2 = 0x1BD11BDAu ^ 42u;
    x0 += ks0; x1 += ks1;
#define TFR(r) { x0 += x1; x1 = (x1 << (r)) | (x1 >> (32 - (r))); x1 ^= x0; }
    TFR(13) TFR(15) TFR(26) TFR(6)   x0 += ks1; x1 += ks2 + 1u;
    TFR(17) TFR(29) TFR(16) TFR(24)  x0 += ks2; x1 += ks0 + 2u;
    TFR(13) TFR(15) TFR(26) TFR(6)   x0 += ks0; x1 += ks1 + 3u;
    TFR(17) TFR(29) TFR(16) TFR(24)  x0 += ks1; x1 += ks2 + 4u;
    TFR(13) TFR(15) TFR(26) TFR(6)   x0 += ks2; x1 += ks0 + 5u;
#undef TFR
}
__device__ __forceinline__ unsigned tf_bit(unsigned idx) {
    unsigned x0 = 0u, x1 = idx;
    threefry42(x0, x1);
    return (~(x0 ^ x1)) >> 31;
}
// mask word w (< 800000): row = w>>3, cols (w&7)*32 .. +31 (cols 0-255 half)
__device__ __forceinline__ void mask_word(unsigned w) {
    unsigned base = (w >> 3) * 512u + (w & 7u) * 32u;
    unsigned m = 0u;
#pragma unroll 8
    for (int j = 0; j < 32; j++)
        m |= tf_bit(base + (unsigned)j) << j;
    g_mask[w] = m;
}

// ---------------- mma.sync / ldmatrix wrappers ----------------------------------
__device__ __forceinline__ void mma_f16(float* c, const unsigned* a, unsigned b0, unsigned b1) {
    asm volatile(
        "mma.sync.aligned.m16n8k16.row.col.f32.f16.f16.f32 "
        "{%0,%1,%2,%3}, {%4,%5,%6,%7}, {%8,%9}, {%0,%1,%2,%3};"
        : "+f"(c[0]), "+f"(c[1]), "+f"(c[2]), "+f"(c[3])
        : "r"(a[0]), "r"(a[1]), "r"(a[2]), "r"(a[3]), "r"(b0), "r"(b1));
}
__device__ __forceinline__ void ldsm_x4(unsigned* r, unsigned addr) {
    asm volatile("ldmatrix.sync.aligned.m8n8.x4.shared.b16 {%0,%1,%2,%3}, [%4];"
                 : "=r"(r[0]), "=r"(r[1]), "=r"(r[2]), "=r"(r[3]) : "r"(addr));
}
__device__ __forceinline__ void ldsm_x4t(unsigned* r, unsigned addr) {
    asm volatile("ldmatrix.sync.aligned.m8n8.x4.trans.shared.b16 {%0,%1,%2,%3}, [%4];"
                 : "=r"(r[0]), "=r"(r[1]), "=r"(r[2]), "=r"(r[3]) : "r"(addr));
}

// ---------------- degree / CSR build (mask words fused in) -----------------------
__global__ void deg_init_kernel() {
    int i = blockIdx.x * blockDim.x + threadIdx.x;
    if (i < NN) g_cnt[i] = 0;
}
// + mask words [0, 266667)
__global__ void deg_count_kernel(const int* __restrict__ dst) {
    int e = blockIdx.x * blockDim.x + threadIdx.x;
    if (e >= EE) return;
    atomicAdd(&g_cnt[dst[e]], 1);
    if (e < 266667) mask_word((unsigned)e);
}
__global__ void scan1_kernel() {
    __shared__ int sc[256];
    int t = threadIdx.x;
    int i = blockIdx.x * 256 + t;
    int val = (i < NN) ? g_cnt[i] : 0;
    if (i < NN) g_deg[i] = rsqrtf((float)val + 1.0f);
    sc[t] = val;
    __syncthreads();
#pragma unroll
    for (int d = 1; d < 256; d <<= 1) {
        int v = (t >= d) ? sc[t - d] : 0;
        __syncthreads();
        sc[t] += v;
        __syncthreads();
    }
    if (i < NN) g_off[i] = sc[t] - val;
    if (t == 255) g_bsum[blockIdx.x] = sc[255];
}
__global__ void scan2_kernel() {
    __shared__ int sc[512];
    int t = threadIdx.x;
    int val = (t < 391) ? g_bsum[t] : 0;
    sc[t] = val;
    __syncthreads();
#pragma unroll
    for (int d = 1; d < 512; d <<= 1) {
        int v = (t >= d) ? sc[t - d] : 0;
        __syncthreads();
        sc[t] += v;
        __syncthreads();
    }
    if (t < 391) g_bsum[t] = sc[t] - val;
}
__global__ void scan3_kernel() {
    int i = blockIdx.x * blockDim.x + threadIdx.x;
    if (i < NN) {
        g_off[i] += g_bsum[i >> 8];
        g_fill[i] = 0;
    }
    if (i == 0) g_off[NN] = EE;
}
// + mask words [533334, 800000)
__global__ void fill_kernel(const int* __restrict__ src, const int* __restrict__ dst) {
    int e = blockIdx.x * blockDim.x + threadIdx.x;
    if (e >= EE) return;
    int s = src[e], d = dst[e];
    int pos = g_off[d] + atomicAdd(&g_fill[d], 1);
    g_csr[pos] = s;
    g_nrm[pos] = g_deg[s] * g_deg[d];
    if (e < 266666) mask_word(533334u + (unsigned)e);
}

// ---------------- combined fp16 conversions (+ mask words [266667, 533334)) -----
__global__ void cvt_kernel(const float* __restrict__ W1, const float* __restrict__ W2,
                           const float* __restrict__ x) {
    int b = blockIdx.x;
    if (b < 42) {
        int t = b * 256 + threadIdx.x;
        if (t < 8192) {
            int idx = t * 8;
            unsigned short h[8];
#pragma unroll
            for (int j = 0; j < 8; j++) {
                __half hh = __float2half_rn(W1[idx + j]);
                h[j] = *reinterpret_cast<unsigned short*>(&hh);
            }
            reinterpret_cast<uint4*>(gW1h)[t] = make_uint4(
                (unsigned)h[0] | ((unsigned)h[1] << 16), (unsigned)h[2] | ((unsigned)h[3] << 16),
                (unsigned)h[4] | ((unsigned)h[5] << 16), (unsigned)h[6] | ((unsigned)h[7] << 16));
        } else if (t < 10752) {
            int i2 = t - 8192;
            int idx = i2 * 8;
            unsigned short h[8];
#pragma unroll
            for (int j = 0; j < 8; j++) {
                __half hh = __float2half_rn(W2[idx + j]);
                h[j] = *reinterpret_cast<unsigned short*>(&hh);
            }
            reinterpret_cast<uint4*>(gW2h)[i2] = make_uint4(
                (unsigned)h[0] | ((unsigned)h[1] << 16), (unsigned)h[2] | ((unsigned)h[3] << 16),
                (unsigned)h[4] | ((unsigned)h[5] << 16), (unsigned)h[6] | ((unsigned)h[7] << 16));
        }
    } else {
        int t = (b - 42) * 256 + threadIdx.x;           // 1.6M slots, 8 elems each
        if (t >= 1600000) return;
        float4 a = reinterpret_cast<const float4*>(x)[t * 2];
        float4 c = reinterpret_cast<const float4*>(x)[t * 2 + 1];
        __half2 p0 = __floats2half2_rn(a.x, a.y);
        __half2 p1 = __floats2half2_rn(a.z, a.w);
        __half2 p2 = __floats2half2_rn(c.x, c.y);
        __half2 p3 = __floats2half2_rn(c.z, c.w);
        reinterpret_cast<uint4*>(gX16)[t] = make_uint4(
            *reinterpret_cast<unsigned*>(&p0), *reinterpret_cast<unsigned*>(&p1),
            *reinterpret_cast<unsigned*>(&p2), *reinterpret_cast<unsigned*>(&p3));
        if (t < 266667) mask_word(266667u + (unsigned)t);
    }
}

// ---------------- layer-1 aggregation: pure fp16 CSR gather ---------------------
__global__ __launch_bounds__(256) void agg1_gather_kernel() {
    int n = blockIdx.x * 8 + (threadIdx.x >> 5);   // warp id = node (grid exact)
    int lane = threadIdx.x & 31;

    const uint2* x2 = reinterpret_cast<const uint2*>(gX16);
    float dn = g_deg[n];
    float s0 = dn * dn;
    uint2 sv = x2[n * 32 + lane];
    float2 sa = __half22float2(*reinterpret_cast<__half2*>(&sv.x));
    float2 sb = __half22float2(*reinterpret_cast<__half2*>(&sv.y));
    float4 acc = make_float4(sa.x * s0, sa.y * s0, sb.x * s0, sb.y * s0);

    int beg = g_off[n], end = g_off[n + 1];
    int j = beg;
    for (; j + 4 <= end; j += 4) {
        int i0 = g_csr[j], i1 = g_csr[j + 1], i2 = g_csr[j + 2], i3 = g_csr[j + 3];
        float n0 = g_nrm[j], n1 = g_nrm[j + 1], n2 = g_nrm[j + 2], n3 = g_nrm[j + 3];
        uint2 v0 = x2[i0 * 32 + lane];
        uint2 v1 = x2[i1 * 32 + lane];
        uint2 v2 = x2[i2 * 32 + lane];
        uint2 v3 = x2[i3 * 32 + lane];
        float2 a0 = __half22float2(*reinterpret_cast<__half2*>(&v0.x));
        float2 b0 = __half22float2(*reinterpret_cast<__half2*>(&v0.y));
        float2 a1 = __half22float2(*reinterpret_cast<__half2*>(&v1.x));
        float2 b1 = __half22float2(*reinterpret_cast<__half2*>(&v1.y));
        float2 a2 = __half22float2(*reinterpret_cast<__half2*>(&v2.x));
        float2 b2 = __half22float2(*reinterpret_cast<__half2*>(&v2.y));
        float2 a3 = __half22float2(*reinterpret_cast<__half2*>(&v3.x));
        float2 b3 = __half22float2(*reinterpret_cast<__half2*>(&v3.y));
        acc.x += n0 * a0.x + n1 * a1.x + n2 * a2.x + n3 * a3.x;
        acc.y += n0 * a0.y + n1 * a1.y + n2 * a2.y + n3 * a3.y;
        acc.z += n0 * b0.x + n1 * b1.x + n2 * b2.x + n3 * b3.x;
        acc.w += n0 * b0.y + n1 * b1.y + n2 * b2.y + n3 * b3.y;
    }
    for (; j < end; j++) {
        int s = g_csr[j];
        float nrm = g_nrm[j];
        uint2 v = x2[s * 32 + lane];
        float2 a = __half22float2(*reinterpret_cast<__half2*>(&v.x));
        float2 b = __half22float2(*reinterpret_cast<__half2*>(&v.y));
        acc.x += nrm * a.x; acc.y += nrm * a.y;
        acc.z += nrm * b.x; acc.w += nrm * b.y;
    }
    __half2 p0 = __floats2half2_rn(acc.x, acc.y);
    __half2 p1 = __floats2half2_rn(acc.z, acc.w);
    *reinterpret_cast<uint2*>(&gA16[n * 128 + lane * 4]) =
        make_uint2(*reinterpret_cast<unsigned*>(&p0), *reinterpret_cast<unsigned*>(&p1));
}

// ---------------- fused GEMM1+GEMM2 ---------------------------------------------
#define SROW 136
#define WROW2 48
__global__ __launch_bounds__(256) void gemm1_fused_kernel(const float* __restrict__ bias,
                                                          float* __restrict__ H) {
    extern __shared__ char dsm[];
    __half* sA  = reinterpret_cast<__half*>(dsm);            // 34816B [128][136]
    __half* sB  = reinterpret_cast<__half*>(dsm + 34816);    // 34816B [128][136]
    __half* sW2 = reinterpret_cast<__half*>(dsm + 69632);    // 49152B [512][48]
    float* sRed = reinterpret_cast<float*>(dsm + 34816);     // reuse sB after loop
    __shared__ float sBias[512];

    const int t = threadIdx.x;
    const int lane = t & 31, wid = t >> 5;
    const int m0 = blockIdx.x * 128;
    const int wm = wid & 3;
    const int wn = wid >> 2;

    sBias[t] = bias[t];
    sBias[256 + t] = bias[256 + t];

#pragma unroll
    for (int i = 0; i < 12; i++) {
        int u = i * 256 + t;
        int k = u / 6, c8 = u - k * 6;
        uint4 v = make_uint4(0u, 0u, 0u, 0u);
        if (c8 < 5) v = *reinterpret_cast<const uint4*>(&gW2h[k * 40 + c8 * 8]);
        *reinterpret_cast<uint4*>(&sW2[k * WROW2 + c8 * 8]) = v;
    }
#pragma unroll
    for (int i = 0; i < 8; i++) {
        int c = i * 256 + t;
        int m = c >> 4, c8 = c & 15;
        int gr = m0 + m;
        uint4 v = make_uint4(0u, 0u, 0u, 0u);
        if (gr < NN) v = *reinterpret_cast<const uint4*>(&gA16[gr * 128 + c8 * 8]);
        *reinterpret_cast<uint4*>(&sA[m * SROW + c8 * 8]) = v;
    }

    const unsigned aBase = smem_u32(sA) +
        ((unsigned)(wm * 32 + (lane & 15)) * SROW + (unsigned)((lane >> 4) * 8)) * 2u;
    const unsigned bBase = smem_u32(sB) +
        ((unsigned)(lane & 15) * SROW + (unsigned)(wn * 64 + ((lane >> 4) << 3))) * 2u;
    const unsigned wBase = smem_u32(sW2) +
        ((unsigned)(lane & 15) * WROW2 + (unsigned)((lane >> 4) * 8)) * 2u;

    const int quad = lane >> 2, qt = lane & 3;

    float acc2[2][5][4];
#pragma unroll
    for (int mf = 0; mf < 2; mf++)
#pragma unroll
        for (int nf = 0; nf < 5; nf++)
#pragma unroll
            for (int q = 0; q < 4; q++) acc2[mf][nf][q] = 0.f;

    for (int nt = 0; nt < 4; nt++) {
        __syncthreads();
#pragma unroll
        for (int i = 0; i < 8; i++) {
            int c = i * 256 + t;
            int k = c >> 4, c8 = c & 15;
            uint4 v = *reinterpret_cast<const uint4*>(&gW1h[k * 512 + nt * 128 + c8 * 8]);
            *reinterpret_cast<uint4*>(&sB[k * SROW + c8 * 8]) = v;
        }
        __syncthreads();

        float acc[2][8][4];
#pragma unroll
        for (int mf = 0; mf < 2; mf++)
#pragma unroll
            for (int nf = 0; nf < 8; nf++)
#pragma unroll
                for (int q = 0; q < 4; q++) acc[mf][nf][q] = 0.f;

#pragma unroll
        for (int ks = 0; ks < 8; ks++) {
            unsigned ah[2][4], bh[4][4];
#pragma unroll
            for (int mf = 0; mf < 2; mf++)
                ldsm_x4(ah[mf], aBase + (unsigned)(mf * 16 * SROW * 2) + (unsigned)(ks * 32));
#pragma unroll
            for (int j = 0; j < 4; j++)
                ldsm_x4t(bh[j], bBase + (unsigned)(ks * 16 * SROW * 2) + (unsigned)(j * 32));
#pragma unroll
            for (int mf = 0; mf < 2; mf++) {
#pragma unroll
                for (int j = 0; j < 4; j++) {
                    mma_f16(acc[mf][2 * j],     ah[mf], bh[j][0], bh[j][1]);
                    mma_f16(acc[mf][2 * j + 1], ah[mf], bh[j][2], bh[j][3]);
                }
            }
        }

        unsigned hm[2][8][2];
#pragma unroll
        for (int mf = 0; mf < 2; mf++)
#pragma unroll
            for (int nf = 0; nf < 8; nf++) { hm[mf][nf][0] = 0u; hm[mf][nf][1] = 0u; }

        const int colbase = nt * 128 + wn * 64;
        const bool lowCols = (nt < 2);
#pragma unroll
        for (int mf = 0; mf < 2; mf++) {
#pragma unroll
            for (int p = 0; p < 2; p++) {
                int row = m0 + wm * 32 + mf * 16 + quad + p * 8;
                if (row >= NN) continue;
                unsigned mw0 = 0u, mw1 = 0u;
                if (lowCols) {
                    mw0 = g_mask[row * 8 + (colbase >> 5)];
                    mw1 = g_mask[row * 8 + (colbase >> 5) + 1];
                }
                const unsigned rowbase = (unsigned)row * 512u + (unsigned)colbase;
                float* hp = H + (size_t)row * 512 + colbase;
#pragma unroll
                for (int nf = 0; nf < 8; nf++) {
                    int cl = nf * 8 + qt * 2;
                    unsigned keep0, keep1;
                    if (lowCols) {
                        unsigned mw = (cl < 32) ? mw0 : mw1;
                        int sh = cl & 31;
                        keep0 = (mw >> (sh + 0)) & 1u;
                        keep1 = (mw >> (sh + 1)) & 1u;
                    } else {
                        keep0 = tf_bit(rowbase + (unsigned)cl);
                        keep1 = tf_bit(rowbase + (unsigned)cl + 1u);
                    }
                    float v0 = fmaxf(acc[mf][nf][p * 2 + 0] + sBias[colbase + cl + 0], 0.f) * 2.f;
                    float v1 = fmaxf(acc[mf][nf][p * 2 + 1] + sBias[colbase + cl + 1], 0.f) * 2.f;
                    float2 o;
                    o.x = keep0 ? v0 : 0.f;
                    o.y = keep1 ? v1 : 0.f;
                    *reinterpret_cast<float2*>(hp + cl) = o;
                    __half2 oh = __floats2half2_rn(o.x, o.y);
                    hm[mf][nf][p] = *reinterpret_cast<unsigned*>(&oh);
                }
            }
        }

#pragma unroll
        for (int j = 0; j < 4; j++) {
            unsigned bw[12];
            unsigned ko = (unsigned)((colbase + j * 16) * WROW2 * 2);
            ldsm_x4t(&bw[0], wBase + ko);
            ldsm_x4t(&bw[4], wBase + ko + 32u);
            ldsm_x4t(&bw[8], wBase + ko + 64u);
#pragma unroll
            for (int mf = 0; mf < 2; mf++) {
                unsigned af[4] = {hm[mf][2 * j][0], hm[mf][2 * j][1],
                                  hm[mf][2 * j + 1][0], hm[mf][2 * j + 1][1]};
                mma_f16(acc2[mf][0], af, bw[0], bw[1]);
                mma_f16(acc2[mf][1], af, bw[2], bw[3]);
                mma_f16(acc2[mf][2], af, bw[4], bw[5]);
                mma_f16(acc2[mf][3], af, bw[6], bw[7]);
                mma_f16(acc2[mf][4], af, bw[8], bw[9]);
            }
        }
    }

    __syncthreads();
    if (wn == 1) {
        float* red = sRed + wm * 32 * 40;
#pragma unroll
        for (int mf = 0; mf < 2; mf++)
#pragma unroll
            for (int p = 0; p < 2; p++) {
                int r = mf * 16 + quad + p * 8;
#pragma unroll
                for (int nf = 0; nf < 5; nf++) {
                    int col = nf * 8 + qt * 2;
                    red[r * 40 + col + 0] = acc2[mf][nf][p * 2 + 0];
                    red[r * 40 + col + 1] = acc2[mf][nf][p * 2 + 1];
                }
            }
    }
    __syncthreads();
    if (wn == 0) {
        const float* red = sRed + wm * 32 * 40;
#pragma unroll
        for (int mf = 0; mf < 2; mf++)
#pragma unroll
            for (int p = 0; p < 2; p++) {
                int r = mf * 16 + quad + p * 8;
                int row = m0 + wm * 32 + r;
                if (row >= NN) continue;
#pragma unroll
                for (int nf = 0; nf < 5; nf++) {
                    int col = nf * 8 + qt * 2;
                    float v0 = acc2[mf][nf][p * 2 + 0] + red[r * 40 + col + 0];
                    float v1 = acc2[mf][nf][p * 2 + 1] + red[r * 40 + col + 1];
                    __half2 oh = __floats2half2_rn(v0, v1);
                    *reinterpret_cast<unsigned*>(&gH2[row * 40 + col]) =
                        *reinterpret_cast<unsigned*>(&oh);
                }
            }
    }
}

// ---------------- layer-2 aggregation: fp16 CSR gather (precomputed nrm) --------
__global__ __launch_bounds__(256) void agg2_gather_kernel(const float* __restrict__ b2,
                                                          float* __restrict__ out) {
    int n = blockIdx.x * 8 + (threadIdx.x >> 5);
    int lane = threadIdx.x & 31;
    int grp = lane >= 30 ? 3 : lane / 10;
    int cl = lane - grp * 10;
    bool act = lane < 30;

    const uint2* h2p = reinterpret_cast<const uint2*>(gH2);
    float dn = g_deg[n];
    float4 acc = make_float4(0.f, 0.f, 0.f, 0.f);
    if (grp == 0) {
        uint2 v = h2p[n * 10 + cl];
        float2 a = __half22float2(*reinterpret_cast<__half2*>(&v.x));
        float2 b = __half22float2(*reinterpret_cast<__half2*>(&v.y));
        float s0 = dn * dn;
        acc = make_float4(a.x * s0, a.y * s0, b.x * s0, b.y * s0);
    }
    int beg = g_off[n], end = g_off[n + 1];
    int j = beg + grp;
    if (act) {
        for (; j + 3 < end; j += 6) {
            int s0i = g_csr[j], s1i = g_csr[j + 3];
            float n0 = g_nrm[j], n1 = g_nrm[j + 3];
            uint2 v0 = h2p[s0i * 10 + cl];
            uint2 v1 = h2p[s1i * 10 + cl];
            float2 a0 = __half22float2(*reinterpret_cast<__half2*>(&v0.x));
            float2 b0 = __half22float2(*reinterpret_cast<__half2*>(&v0.y));
            float2 a1 = __half22float2(*reinterpret_cast<__half2*>(&v1.x));
            float2 b1 = __half22float2(*reinterpret_cast<__half2*>(&v1.y));
            acc.x += n0 * a0.x + n1 * a1.x;
            acc.y += n0 * a0.y + n1 * a1.y;
            acc.z += n0 * b0.x + n1 * b1.x;
            acc.w += n0 * b0.y + n1 * b1.y;
        }
        for (; j < end; j += 3) {
            int s = g_csr[j];
            float nrm = g_nrm[j];
            uint2 v = h2p[s * 10 + cl];
            float2 a = __half22float2(*reinterpret_cast<__half2*>(&v.x));
            float2 b = __half22float2(*reinterpret_cast<__half2*>(&v.y));
            acc.x += nrm * a.x; acc.y += nrm * a.y;
            acc.z += nrm * b.x; acc.w += nrm * b.y;
        }
    }
    const unsigned FULL = 0xFFFFFFFFu;
    acc.x += __shfl_down_sync(FULL, acc.x, 10) + __shfl_down_sync(FULL, acc.x, 20);
    acc.y += __shfl_down_sync(FULL, acc.y, 10) + __shfl_down_sync(FULL, acc.y, 20);
    acc.z += __shfl_down_sync(FULL, acc.z, 10) + __shfl_down_sync(FULL, acc.z, 20);
    acc.w += __shfl_down_sync(FULL, acc.w, 10) + __shfl_down_sync(FULL, acc.w, 20);
    if (lane < 10) {
        float4 bb = *reinterpret_cast<const float4*>(&b2[cl * 4]);
        *reinterpret_cast<float4*>(&out[n * 40 + cl * 4]) =
            make_float4(acc.x + bb.x, acc.y + bb.y, acc.z + bb.z, acc.w + bb.w);
    }
}

// ---------------- launch --------------------------------------------------------
extern "C" void kernel_launch(void* const* d_in, const int* in_sizes, int n_in,
                              void* d_out, int out_size) {
    const float* x  = (const float*)d_in[0];
    const int*   ei = (const int*)d_in[1];
    const float* W1 = (const float*)d_in[2];
    const float* b1 = (const float*)d_in[3];
    const float* W2 = (const float*)d_in[4];
    const float* b2 = (const float*)d_in[5];
    (void)in_sizes; (void)n_in; (void)out_size;

    float* out = (float*)d_out;           // [NN, 40]
    float* hidden = out + NN * 40;        // [NN, 512]
    const int* src = ei;
    const int* dst = ei + EE;

    const int FUSED_SMEM = 118784;        // A(34816) + B(34816) + W2(49152)
    cudaFuncSetAttribute(gemm1_fused_kernel,
                         cudaFuncAttributeMaxDynamicSharedMemorySize, FUSED_SMEM);

    // degree + CSR build + fp16 conversions; mask cols 0-255 distributed into
    // the memory-bound preamble kernels (hidden under their stalls)
    deg_init_kernel<<<(NN + 255) / 256, 256>>>();
    deg_count_kernel<<<(EE + 255) / 256, 256>>>(dst);     // + mask words 0..266666
    cvt_kernel<<<6292, 256>>>(W1, W2, x);                 // + mask words 266667..533333
    scan1_kernel<<<391, 256>>>();
    scan2_kernel<<<1, 512>>>();
    scan3_kernel<<<(NN + 255) / 256, 256>>>();
    fill_kernel<<<(EE + 255) / 256, 256>>>(src, dst);     // + mask words 533334..799999

    // layer-1 aggregation (pure gather)
    agg1_gather_kernel<<<12500, 256>>>();

    // fused GEMM1 (+ dropout/relu + H store) + GEMM2 (-> gH2 fp16)
    gemm1_fused_kernel<<<(NN + 127) / 128, 256, FUSED_SMEM>>>(b1, hidden);

    // layer-2 aggregation + fused b2
    agg2_gather_kernel<<<12500, 256>>>(b2, out);
}

// round 17
// speedup vs baseline: 1.1184x; 1.1184x over previous
#include <cuda_runtime.h>
#include <cuda_fp16.h>
#include <cstdint>

#define NN 100000
#define EE 800000

// ---------------- scratch (__device__ globals; no allocation allowed) ----------
__device__ float g_deg[NN];                       // dinv_sqrt
__device__ int   g_cnt[NN];                       // in-degree counts
__device__ int   g_off[NN + 1];                   // CSR offsets (by dst)
__device__ int   g_fill[NN];                      // fill cursors
__device__ int   g_csr[EE];                       // src ids grouped by dst
__device__ int   g_bsum[512];                     // scan block sums
__device__ __align__(16) __half gX16[NN * 128];   // x in fp16 (agg1 gather source)
__device__ __align__(16) __half gA16[NN * 128];   // aggregated X, fp16 (GEMM1 A)
__device__ __align__(16) __half gH2[NN * 40];     // H @ W2, fp16 (agg2 source)
__device__ unsigned g_mask[800000];               // keep-bits for cols 0-255 only
__device__ __align__(16) __half gW1h[128 * 512];  // W1 fp16, k-major
__device__ __align__(16) __half gW2h[512 * 40];   // W2 fp16, k-major

// ---------------- small helpers ------------------------------------------------
__device__ __forceinline__ unsigned smem_u32(const void* p) {
    unsigned a;
    asm("{ .reg .u64 t; cvta.to.shared.u64 t, %1; cvt.u32.u64 %0, t; }" : "=r"(a) : "l"(p));
    return a;
}

// JAX threefry2x32 with key = (0, 42)
__device__ __forceinline__ void threefry42(unsigned& x0, unsigned& x1) {
    const unsigned ks0 = 0u, ks1 = 42u, ks2 = 0x1BD11BDAu ^ 42u;
    x0 += ks0; x1 += ks1;
#define TFR(r) { x0 += x1; x1 = (x1 << (r)) | (x1 >> (32 - (r))); x1 ^= x0; }
    TFR(13) TFR(15) TFR(26) TFR(6)   x0 += ks1; x1 += ks2 + 1u;
    TFR(17) TFR(29) TFR(16) TFR(24)  x0 += ks2; x1 += ks0 + 2u;
    TFR(13) TFR(15) TFR(26) TFR(6)   x0 += ks0; x1 += ks1 + 3u;
    TFR(17) TFR(29) TFR(16) TFR(24)  x0 += ks1; x1 += ks2 + 4u;
    TFR(13) TFR(15) TFR(26) TFR(6)   x0 += ks2; x1 += ks0 + 5u;
#undef TFR
}
__device__ __forceinline__ unsigned tf_bit(unsigned idx) {
    unsigned x0 = 0u, x1 = idx;
    threefry42(x0, x1);
    return (~(x0 ^ x1)) >> 31;
}

// ---------------- mma.sync / ldmatrix wrappers ----------------------------------
__device__ __forceinline__ void mma_f16(float* c, const unsigned* a, unsigned b0, unsigned b1) {
    asm volatile(
        "mma.sync.aligned.m16n8k16.row.col.f32.f16.f16.f32 "
        "{%0,%1,%2,%3}, {%4,%5,%6,%7}, {%8,%9}, {%0,%1,%2,%3};"
        : "+f"(c[0]), "+f"(c[1]), "+f"(c[2]), "+f"(c[3])
        : "r"(a[0]), "r"(a[1]), "r"(a[2]), "r"(a[3]), "r"(b0), "r"(b1));
}
__device__ __forceinline__ void ldsm_x4(unsigned* r, unsigned addr) {
    asm volatile("ldmatrix.sync.aligned.m8n8.x4.shared.b16 {%0,%1,%2,%3}, [%4];"
                 : "=r"(r[0]), "=r"(r[1]), "=r"(r[2]), "=r"(r[3]) : "r"(addr));
}
__device__ __forceinline__ void ldsm_x4t(unsigned* r, unsigned addr) {
    asm volatile("ldmatrix.sync.aligned.m8n8.x4.trans.shared.b16 {%0,%1,%2,%3}, [%4];"
                 : "=r"(r[0]), "=r"(r[1]), "=r"(r[2]), "=r"(r[3]) : "r"(addr));
}

// ---------------- degree / CSR build --------------------------------------------
__global__ void deg_init_kernel() {
    int i = blockIdx.x * blockDim.x + threadIdx.x;
    if (i < NN) g_cnt[i] = 0;
}
__global__ void deg_count_kernel(const int* __restrict__ dst) {
    int e = blockIdx.x * blockDim.x + threadIdx.x;
    if (e < EE) atomicAdd(&g_cnt[dst[e]], 1);
}
__global__ void scan1_kernel() {
    __shared__ int sc[256];
    int t = threadIdx.x;
    int i = blockIdx.x * 256 + t;
    int val = (i < NN) ? g_cnt[i] : 0;
    if (i < NN) g_deg[i] = rsqrtf((float)val + 1.0f);
    sc[t] = val;
    __syncthreads();
#pragma unroll
    for (int d = 1; d < 256; d <<= 1) {
        int v = (t >= d) ? sc[t - d] : 0;
        __syncthreads();
        sc[t] += v;
        __syncthreads();
    }
    if (i < NN) g_off[i] = sc[t] - val;
    if (t == 255) g_bsum[blockIdx.x] = sc[255];
}
__global__ void scan2_kernel() {
    __shared__ int sc[512];
    int t = threadIdx.x;
    int val = (t < 391) ? g_bsum[t] : 0;
    sc[t] = val;
    __syncthreads();
#pragma unroll
    for (int d = 1; d < 512; d <<= 1) {
        int v = (t >= d) ? sc[t - d] : 0;
        __syncthreads();
        sc[t] += v;
        __syncthreads();
    }
    if (t < 391) g_bsum[t] = sc[t] - val;
}
__global__ void scan3_kernel() {
    int i = blockIdx.x * blockDim.x + threadIdx.x;
    if (i < NN) {
        g_off[i] += g_bsum[i >> 8];
        g_fill[i] = 0;
    }
    if (i == 0) g_off[NN] = EE;
}
__global__ void fill_kernel(const int* __restrict__ src, const int* __restrict__ dst) {
    int e = blockIdx.x * blockDim.x + threadIdx.x;
    if (e >= EE) return;
    int d = dst[e];
    int pos = g_off[d] + atomicAdd(&g_fill[d], 1);
    g_csr[pos] = src[e];
}

// ---------------- combined fp16 conversions: W1, W2, x --------------------------
__global__ void cvt_kernel(const float* __restrict__ W1, const float* __restrict__ W2,
                           const float* __restrict__ x) {
    int b = blockIdx.x;
    if (b < 42) {
        int t = b * 256 + threadIdx.x;
        if (t < 8192) {
            int idx = t * 8;
            unsigned short h[8];
#pragma unroll
            for (int j = 0; j < 8; j++) {
                __half hh = __float2half_rn(W1[idx + j]);
                h[j] = *reinterpret_cast<unsigned short*>(&hh);
            }
            reinterpret_cast<uint4*>(gW1h)[t] = make_uint4(
                (unsigned)h[0] | ((unsigned)h[1] << 16), (unsigned)h[2] | ((unsigned)h[3] << 16),
                (unsigned)h[4] | ((unsigned)h[5] << 16), (unsigned)h[6] | ((unsigned)h[7] << 16));
        } else if (t < 10752) {
            int i2 = t - 8192;
            int idx = i2 * 8;
            unsigned short h[8];
#pragma unroll
            for (int j = 0; j < 8; j++) {
                __half hh = __float2half_rn(W2[idx + j]);
                h[j] = *reinterpret_cast<unsigned short*>(&hh);
            }
            reinterpret_cast<uint4*>(gW2h)[i2] = make_uint4(
                (unsigned)h[0] | ((unsigned)h[1] << 16), (unsigned)h[2] | ((unsigned)h[3] << 16),
                (unsigned)h[4] | ((unsigned)h[5] << 16), (unsigned)h[6] | ((unsigned)h[7] << 16));
        }
    } else {
        int t = (b - 42) * 256 + threadIdx.x;           // 1.6M slots, 8 elems each
        if (t >= 1600000) return;
        float4 a = reinterpret_cast<const float4*>(x)[t * 2];
        float4 c = reinterpret_cast<const float4*>(x)[t * 2 + 1];
        __half2 p0 = __floats2half2_rn(a.x, a.y);
        __half2 p1 = __floats2half2_rn(a.z, a.w);
        __half2 p2 = __floats2half2_rn(c.x, c.y);
        __half2 p3 = __floats2half2_rn(c.z, c.w);
        reinterpret_cast<uint4*>(gX16)[t] = make_uint4(
            *reinterpret_cast<unsigned*>(&p0), *reinterpret_cast<unsigned*>(&p1),
            *reinterpret_cast<unsigned*>(&p2), *reinterpret_cast<unsigned*>(&p3));
    }
}

// ---------------- layer-1 aggregation: fp16 CSR gather (MLP=4) + half mask ------
__global__ __launch_bounds__(256) void agg1_gather_kernel() {
    int n = blockIdx.x * 8 + (threadIdx.x >> 5);   // warp id = node (grid exact)
    int lane = threadIdx.x & 31;

    const uint2* x2 = reinterpret_cast<const uint2*>(gX16);
    float dn = g_deg[n];
    float s0 = dn * dn;
    uint2 sv = x2[n * 32 + lane];
    float2 sa = __half22float2(*reinterpret_cast<__half2*>(&sv.x));
    float2 sb = __half22float2(*reinterpret_cast<__half2*>(&sv.y));
    float4 acc = make_float4(sa.x * s0, sa.y * s0, sb.x * s0, sb.y * s0);

    int beg = g_off[n], end = g_off[n + 1];
    int j = beg;
    for (; j + 4 <= end; j += 4) {
        int i0 = g_csr[j], i1 = g_csr[j + 1], i2 = g_csr[j + 2], i3 = g_csr[j + 3];
        float n0 = g_deg[i0] * dn, n1 = g_deg[i1] * dn;
        float n2 = g_deg[i2] * dn, n3 = g_deg[i3] * dn;
        uint2 v0 = x2[i0 * 32 + lane];
        uint2 v1 = x2[i1 * 32 + lane];
        uint2 v2 = x2[i2 * 32 + lane];
        uint2 v3 = x2[i3 * 32 + lane];
        float2 a0 = __half22float2(*reinterpret_cast<__half2*>(&v0.x));
        float2 b0 = __half22float2(*reinterpret_cast<__half2*>(&v0.y));
        float2 a1 = __half22float2(*reinterpret_cast<__half2*>(&v1.x));
        float2 b1 = __half22float2(*reinterpret_cast<__half2*>(&v1.y));
        float2 a2 = __half22float2(*reinterpret_cast<__half2*>(&v2.x));
        float2 b2 = __half22float2(*reinterpret_cast<__half2*>(&v2.y));
        float2 a3 = __half22float2(*reinterpret_cast<__half2*>(&v3.x));
        float2 b3 = __half22float2(*reinterpret_cast<__half2*>(&v3.y));
        acc.x += n0 * a0.x + n1 * a1.x + n2 * a2.x + n3 * a3.x;
        acc.y += n0 * a0.y + n1 * a1.y + n2 * a2.y + n3 * a3.y;
        acc.z += n0 * b0.x + n1 * b1.x + n2 * b2.x + n3 * b3.x;
        acc.w += n0 * b0.y + n1 * b1.y + n2 * b2.y + n3 * b3.y;
    }
    for (; j < end; j++) {
        int s = g_csr[j];
        float nrm = g_deg[s] * dn;
        uint2 v = x2[s * 32 + lane];
        float2 a = __half22float2(*reinterpret_cast<__half2*>(&v.x));
        float2 b = __half22float2(*reinterpret_cast<__half2*>(&v.y));
        acc.x += nrm * a.x; acc.y += nrm * a.y;
        acc.z += nrm * b.x; acc.w += nrm * b.y;
    }
    __half2 p0 = __floats2half2_rn(acc.x, acc.y);
    __half2 p1 = __floats2half2_rn(acc.z, acc.w);
    *reinterpret_cast<uint2*>(&gA16[n * 128 + lane * 4]) =
        make_uint2(*reinterpret_cast<unsigned*>(&p0), *reinterpret_cast<unsigned*>(&p1));

    // dropout mask for hidden row n, cols 0-255 (8 words); cols 256-511 inline in gemm1
    unsigned base = (unsigned)n * 512u + (unsigned)lane;
#pragma unroll
    for (int w = 0; w < 8; w++) {
        unsigned bit = tf_bit(base + (unsigned)w * 32u);
        unsigned word = __ballot_sync(0xFFFFFFFFu, bit);
        if (lane == 0) g_mask[n * 8 + w] = word;
    }
}

// ---------------- fused GEMM1+GEMM2 (W2 sliced per nt -> 2 CTAs/SM) --------------
#define SROW 136
#define WROW2 48
__global__ __launch_bounds__(256, 2) void gemm1_fused_kernel(const float* __restrict__ bias,
                                                             float* __restrict__ H) {
    extern __shared__ char dsm[];
    __half* sA  = reinterpret_cast<__half*>(dsm);            // 34816B [128][136]
    __half* sB  = reinterpret_cast<__half*>(dsm + 34816);    // 34816B [128][136]
    __half* sW2 = reinterpret_cast<__half*>(dsm + 69632);    // 12288B [128][48] slice
    float* sRed = reinterpret_cast<float*>(dsm + 34816);     // reuse sB after loop
    __shared__ float sBias[512];

    const int t = threadIdx.x;
    const int lane = t & 31, wid = t >> 5;
    const int m0 = blockIdx.x * 128;
    const int wm = wid & 3;
    const int wn = wid >> 2;

    sBias[t] = bias[t];
    sBias[256 + t] = bias[256 + t];

    // A tile (loaded once)
#pragma unroll
    for (int i = 0; i < 8; i++) {
        int c = i * 256 + t;
        int m = c >> 4, c8 = c & 15;
        int gr = m0 + m;
        uint4 v = make_uint4(0u, 0u, 0u, 0u);
        if (gr < NN) v = *reinterpret_cast<const uint4*>(&gA16[gr * 128 + c8 * 8]);
        *reinterpret_cast<uint4*>(&sA[m * SROW + c8 * 8]) = v;
    }

    const unsigned aBase = smem_u32(sA) +
        ((unsigned)(wm * 32 + (lane & 15)) * SROW + (unsigned)((lane >> 4) * 8)) * 2u;
    const unsigned bBase = smem_u32(sB) +
        ((unsigned)(lane & 15) * SROW + (unsigned)(wn * 64 + ((lane >> 4) << 3))) * 2u;
    const unsigned wBase = smem_u32(sW2) +
        ((unsigned)(lane & 15) * WROW2 + (unsigned)((lane >> 4) * 8)) * 2u;

    const int quad = lane >> 2, qt = lane & 3;

    float acc2[2][5][4];
#pragma unroll
    for (int mf = 0; mf < 2; mf++)
#pragma unroll
        for (int nf = 0; nf < 5; nf++)
#pragma unroll
            for (int q = 0; q < 4; q++) acc2[mf][nf][q] = 0.f;

    for (int nt = 0; nt < 4; nt++) {
        __syncthreads();   // prev stage-2 done (and initial A load on nt=0)
        // W1 tile nt
#pragma unroll
        for (int i = 0; i < 8; i++) {
            int c = i * 256 + t;
            int k = c >> 4, c8 = c & 15;
            uint4 v = *reinterpret_cast<const uint4*>(&gW1h[k * 512 + nt * 128 + c8 * 8]);
            *reinterpret_cast<uint4*>(&sB[k * SROW + c8 * 8]) = v;
        }
        // W2 slice: rows nt*128 .. nt*128+127 into [128][48] (pad cols 40-47)
#pragma unroll
        for (int i = 0; i < 3; i++) {
            int u = i * 256 + t;              // 768 uint4 slots
            int k = u / 6, c8 = u - k * 6;
            uint4 v = make_uint4(0u, 0u, 0u, 0u);
            if (c8 < 5) v = *reinterpret_cast<const uint4*>(&gW2h[(nt * 128 + k) * 40 + c8 * 8]);
            *reinterpret_cast<uint4*>(&sW2[k * WROW2 + c8 * 8]) = v;
        }
        __syncthreads();

        float acc[2][8][4];
#pragma unroll
        for (int mf = 0; mf < 2; mf++)
#pragma unroll
            for (int nf = 0; nf < 8; nf++)
#pragma unroll
                for (int q = 0; q < 4; q++) acc[mf][nf][q] = 0.f;

#pragma unroll
        for (int ks = 0; ks < 8; ks++) {
            unsigned ah[2][4], bh[4][4];
#pragma unroll
            for (int mf = 0; mf < 2; mf++)
                ldsm_x4(ah[mf], aBase + (unsigned)(mf * 16 * SROW * 2) + (unsigned)(ks * 32));
#pragma unroll
            for (int j = 0; j < 4; j++)
                ldsm_x4t(bh[j], bBase + (unsigned)(ks * 16 * SROW * 2) + (unsigned)(j * 32));
#pragma unroll
            for (int mf = 0; mf < 2; mf++) {
#pragma unroll
                for (int j = 0; j < 4; j++) {
                    mma_f16(acc[mf][2 * j],     ah[mf], bh[j][0], bh[j][1]);
                    mma_f16(acc[mf][2 * j + 1], ah[mf], bh[j][2], bh[j][3]);
                }
            }
        }

        unsigned hm[2][8][2];
#pragma unroll
        for (int mf = 0; mf < 2; mf++)
#pragma unroll
            for (int nf = 0; nf < 8; nf++) { hm[mf][nf][0] = 0u; hm[mf][nf][1] = 0u; }

        const int colbase = nt * 128 + wn * 64;
        const bool lowCols = (nt < 2);
#pragma unroll
        for (int mf = 0; mf < 2; mf++) {
#pragma unroll
            for (int p = 0; p < 2; p++) {
                int row = m0 + wm * 32 + mf * 16 + quad + p * 8;
                if (row >= NN) continue;
                unsigned mw0 = 0u, mw1 = 0u;
                if (lowCols) {
                    mw0 = g_mask[row * 8 + (colbase >> 5)];
                    mw1 = g_mask[row * 8 + (colbase >> 5) + 1];
                }
                const unsigned rowbase = (unsigned)row * 512u + (unsigned)colbase;
                float* hp = H + (size_t)row * 512 + colbase;
#pragma unroll
                for (int nf = 0; nf < 8; nf++) {
                    int cl = nf * 8 + qt * 2;
                    unsigned keep0, keep1;
                    if (lowCols) {
                        unsigned mw = (cl < 32) ? mw0 : mw1;
                        int sh = cl & 31;
                        keep0 = (mw >> (sh + 0)) & 1u;
                        keep1 = (mw >> (sh + 1)) & 1u;
                    } else {
                        keep0 = tf_bit(rowbase + (unsigned)cl);
                        keep1 = tf_bit(rowbase + (unsigned)cl + 1u);
                    }
                    float v0 = fmaxf(acc[mf][nf][p * 2 + 0] + sBias[colbase + cl + 0], 0.f) * 2.f;
                    float v1 = fmaxf(acc[mf][nf][p * 2 + 1] + sBias[colbase + cl + 1], 0.f) * 2.f;
                    float2 o;
                    o.x = keep0 ? v0 : 0.f;
                    o.y = keep1 ? v1 : 0.f;
                    *reinterpret_cast<float2*>(hp + cl) = o;
                    __half2 oh = __floats2half2_rn(o.x, o.y);
                    hm[mf][nf][p] = *reinterpret_cast<unsigned*>(&oh);
                }
            }
        }

        // stage-2: k rows local to this nt slice are wn*64 + j*16
#pragma unroll
        for (int j = 0; j < 4; j++) {
            unsigned bw[12];
            unsigned ko = (unsigned)((wn * 64 + j * 16) * WROW2 * 2);
            ldsm_x4t(&bw[0], wBase + ko);
            ldsm_x4t(&bw[4], wBase + ko + 32u);
            ldsm_x4t(&bw[8], wBase + ko + 64u);
#pragma unroll
            for (int mf = 0; mf < 2; mf++) {
                unsigned af[4] = {hm[mf][2 * j][0], hm[mf][2 * j][1],
                                  hm[mf][2 * j + 1][0], hm[mf][2 * j + 1][1]};
                mma_f16(acc2[mf][0], af, bw[0], bw[1]);
                mma_f16(acc2[mf][1], af, bw[2], bw[3]);
                mma_f16(acc2[mf][2], af, bw[4], bw[5]);
                mma_f16(acc2[mf][3], af, bw[6], bw[7]);
                mma_f16(acc2[mf][4], af, bw[8], bw[9]);
            }
        }
    }

    __syncthreads();
    if (wn == 1) {
        float* red = sRed + wm * 32 * 40;
#pragma unroll
        for (int mf = 0; mf < 2; mf++)
#pragma unroll
            for (int p = 0; p < 2; p++) {
                int r = mf * 16 + quad + p * 8;
#pragma unroll
                for (int nf = 0; nf < 5; nf++) {
                    int col = nf * 8 + qt * 2;
                    red[r * 40 + col + 0] = acc2[mf][nf][p * 2 + 0];
                    red[r * 40 + col + 1] = acc2[mf][nf][p * 2 + 1];
                }
            }
    }
    __syncthreads();
    if (wn == 0) {
        const float* red = sRed + wm * 32 * 40;
#pragma unroll
        for (int mf = 0; mf < 2; mf++)
#pragma unroll
            for (int p = 0; p < 2; p++) {
                int r = mf * 16 + quad + p * 8;
                int row = m0 + wm * 32 + r;
                if (row >= NN) continue;
#pragma unroll
                for (int nf = 0; nf < 5; nf++) {
                    int col = nf * 8 + qt * 2;
                    float v0 = acc2[mf][nf][p * 2 + 0] + red[r * 40 + col + 0];
                    float v1 = acc2[mf][nf][p * 2 + 1] + red[r * 40 + col + 1];
                    __half2 oh = __floats2half2_rn(v0, v1);
                    *reinterpret_cast<unsigned*>(&gH2[row * 40 + col]) =
                        *reinterpret_cast<unsigned*>(&oh);
                }
            }
    }
}

// ---------------- layer-2 aggregation: fp16 CSR gather (unroll 2) ---------------
__global__ __launch_bounds__(256) void agg2_gather_kernel(const float* __restrict__ b2,
                                                          float* __restrict__ out) {
    int n = blockIdx.x * 8 + (threadIdx.x >> 5);
    int lane = threadIdx.x & 31;
    int grp = lane >= 30 ? 3 : lane / 10;
    int cl = lane - grp * 10;
    bool act = lane < 30;

    const uint2* h2p = reinterpret_cast<const uint2*>(gH2);
    float dn = g_deg[n];
    float4 acc = make_float4(0.f, 0.f, 0.f, 0.f);
    if (grp == 0) {
        uint2 v = h2p[n * 10 + cl];
        float2 a = __half22float2(*reinterpret_cast<__half2*>(&v.x));
        float2 b = __half22float2(*reinterpret_cast<__half2*>(&v.y));
        float s0 = dn * dn;
        acc = make_float4(a.x * s0, a.y * s0, b.x * s0, b.y * s0);
    }
    int beg = g_off[n], end = g_off[n + 1];
    int j = beg + grp;
    if (act) {
        for (; j + 3 < end; j += 6) {
            int s0i = g_csr[j], s1i = g_csr[j + 3];
            float n0 = g_deg[s0i] * dn, n1 = g_deg[s1i] * dn;
            uint2 v0 = h2p[s0i * 10 + cl];
            uint2 v1 = h2p[s1i * 10 + cl];
            float2 a0 = __half22float2(*reinterpret_cast<__half2*>(&v0.x));
            float2 b0 = __half22float2(*reinterpret_cast<__half2*>(&v0.y));
            float2 a1 = __half22float2(*reinterpret_cast<__half2*>(&v1.x));
            float2 b1 = __half22float2(*reinterpret_cast<__half2*>(&v1.y));
            acc.x += n0 * a0.x + n1 * a1.x;
            acc.y += n0 * a0.y + n1 * a1.y;
            acc.z += n0 * b0.x + n1 * b1.x;
            acc.w += n0 * b0.y + n1 * b1.y;
        }
        for (; j < end; j += 3) {
            int s = g_csr[j];
            float nrm = g_deg[s] * dn;
            uint2 v = h2p[s * 10 + cl];
            float2 a = __half22float2(*reinterpret_cast<__half2*>(&v.x));
            float2 b = __half22float2(*reinterpret_cast<__half2*>(&v.y));
            acc.x += nrm * a.x; acc.y += nrm * a.y;
            acc.z += nrm * b.x; acc.w += nrm * b.y;
        }
    }
    const unsigned FULL = 0xFFFFFFFFu;
    acc.x += __shfl_down_sync(FULL, acc.x, 10) + __shfl_down_sync(FULL, acc.x, 20);
    acc.y += __shfl_down_sync(FULL, acc.y, 10) + __shfl_down_sync(FULL, acc.y, 20);
    acc.z += __shfl_down_sync(FULL, acc.z, 10) + __shfl_down_sync(FULL, acc.z, 20);
    acc.w += __shfl_down_sync(FULL, acc.w, 10) + __shfl_down_sync(FULL, acc.w, 20);
    if (lane < 10) {
        float4 bb = *reinterpret_cast<const float4*>(&b2[cl * 4]);
        *reinterpret_cast<float4*>(&out[n * 40 + cl * 4]) =
            make_float4(acc.x + bb.x, acc.y + bb.y, acc.z + bb.z, acc.w + bb.w);
    }
}

// ---------------- launch --------------------------------------------------------
extern "C" void kernel_launch(void* const* d_in, const int* in_sizes, int n_in,
                              void* d_out, int out_size) {
    const float* x  = (const float*)d_in[0];
    const int*   ei = (const int*)d_in[1];
    const float* W1 = (const float*)d_in[2];
    const float* b1 = (const float*)d_in[3];
    const float* W2 = (const float*)d_in[4];
    const float* b2 = (const float*)d_in[5];
    (void)in_sizes; (void)n_in; (void)out_size;

    float* out = (float*)d_out;           // [NN, 40]
    float* hidden = out + NN * 40;        // [NN, 512]
    const int* src = ei;
    const int* dst = ei + EE;

    const int FUSED_SMEM = 81920;         // A(34816) + B(34816) + W2 slice(12288)
    cudaFuncSetAttribute(gemm1_fused_kernel,
                         cudaFuncAttributeMaxDynamicSharedMemorySize, FUSED_SMEM);

    // degree + CSR build + fp16 conversions
    deg_init_kernel<<<(NN + 255) / 256, 256>>>();
    deg_count_kernel<<<(EE + 255) / 256, 256>>>(dst);
    cvt_kernel<<<6292, 256>>>(W1, W2, x);
    scan1_kernel<<<391, 256>>>();         // also finalizes g_deg
    scan2_kernel<<<1, 512>>>();
    scan3_kernel<<<(NN + 255) / 256, 256>>>();
    fill_kernel<<<(EE + 255) / 256, 256>>>(src, dst);

    // layer-1 aggregation + mask cols 0-255
    agg1_gather_kernel<<<12500, 256>>>();

    // fused GEMM1 (+ dropout/relu + H store) + GEMM2 (-> gH2 fp16), 2 CTAs/SM
    gemm1_fused_kernel<<<(NN + 127) / 128, 256, FUSED_SMEM>>>(b1, hidden);

    // layer-2 aggregation + fused b2
    agg2_gather_kernel<<<12500, 256>>>(b2, out);
}